// round 12
// baseline (speedup 1.0000x reference)
#include <cuda_runtime.h>
#include <cuda_bf16.h>
#include <cstdint>
#include <cstddef>

// Problem constants
static constexpr int N     = 100000;   // nodes
static constexpr int NPAD  = 100096;   // padded to 782*128
static constexpr int E     = 1600000;  // edges
static constexpr int NREL  = 8;
static constexpr int D     = 128;      // embed == hidden
static constexpr int G     = 64;       // graphs
static constexpr int NC    = 49;       // output classes
static constexpr int ROWTILES = NPAD / 128;  // 782
static constexpr int M     = N * NREL;       // 800000 (dst,rel) buckets
static constexpr int SBLK  = 1024;           // scan block size
static constexpr int NSB   = (M + SBLK - 1) / SBLK;  // 782 scan blocks
static constexpr int GEMM_BX = 16;           // persistent blocks per ct (16*9=144 <= 148)

// Scratch (static device globals; no runtime allocation)
__device__ __nv_bfloat16 g_xr[(size_t)NREL * NPAD * D]; // 205 MB messages (bf16)
__device__ float    g_agg[(size_t)NPAD * D];   // 51 MB: root@w + bias seed
__device__ int      g_cnt[M];                  // per (dst,rel) in-degree
__device__ float    g_rinv[M];                 // 1/max(cnt,1) precomputed
__device__ int      g_rowstart[M];             // CSR starts (exclusive scan of cnt)
__device__ int      g_cursor[M];               // fill cursors
__device__ int      g_bsum[NSB];               // scan partials
__device__ int      g_boff[NSB];               // scanned partials
__device__ unsigned g_erec[E];                 // packed (src | t<<20), bucketed
__device__ float    g_segsum[G * D];
__device__ float    g_segcnt[G];
__device__ int      g_is64;

// ---------------------------------------------------------------------------
// int64-vs-int32 index helper (decided at runtime by detector in k_zero)
// ---------------------------------------------------------------------------
__device__ __forceinline__ long long ldidx(const void* p, long long i, int is64) {
    if (is64) return ((const long long*)p)[i];
    return (long long)((const int*)p)[i];
}

// ---------------------------------------------------------------------------
// Zero accumulators + int64 detection (fused; one launch).
// Detector: edge_index values are random in [0,100000). If the buffer is
// int64, every odd 32-bit word (high half) is zero; if int32 those words are
// random node ids (P[all 64 zero] ~ 0).
// ---------------------------------------------------------------------------
__global__ void k_zero(const unsigned* ei_words) {
    int i = blockIdx.x * blockDim.x + threadIdx.x;
    if (i < M)     g_cnt[i] = 0;
    if (i < G * D) g_segsum[i] = 0.0f;
    if (i < G)     g_segcnt[i] = 0.0f;
    if (i == 0) {
        int is64 = 1;
        for (int k = 0; k < 64; k++) {
            if (ei_words[2 * k + 1] != 0u) { is64 = 0; break; }
        }
        g_is64 = is64;
    }
}

// ---------------------------------------------------------------------------
// Histogram: in-degree per (dst, rel)
// ---------------------------------------------------------------------------
__global__ void k_count(const void* ei, const void* et) {
    int e = blockIdx.x * blockDim.x + threadIdx.x;
    if (e >= E) return;
    int is64 = g_is64;
    int dst = (int)ldidx(ei, (long long)E + e, is64);
    int t   = (int)ldidx(et, e, is64);
    atomicAdd(&g_cnt[dst * NREL + t], 1);
}

// ---------------------------------------------------------------------------
// Exclusive scan of g_cnt (3 kernels). Produces g_rowstart, inits g_cursor,
// and precomputes g_rinv = 1/max(cnt,1).
// ---------------------------------------------------------------------------
__global__ void __launch_bounds__(SBLK) k_scan1() {
    __shared__ int sm[SBLK];
    int t = threadIdx.x;
    int i = blockIdx.x * SBLK + t;
    int v = (i < M) ? g_cnt[i] : 0;
    sm[t] = v;
    __syncthreads();
    #pragma unroll
    for (int off = 1; off < SBLK; off <<= 1) {
        int x = (t >= off) ? sm[t - off] : 0;
        __syncthreads();
        sm[t] += x;
        __syncthreads();
    }
    if (i < M) g_rowstart[i] = sm[t] - v;
    if (t == SBLK - 1) g_bsum[blockIdx.x] = sm[t];
}

__global__ void __launch_bounds__(SBLK) k_scan2() {
    __shared__ int sm[SBLK];
    int t = threadIdx.x;
    int v = (t < NSB) ? g_bsum[t] : 0;
    sm[t] = v;
    __syncthreads();
    #pragma unroll
    for (int off = 1; off < SBLK; off <<= 1) {
        int x = (t >= off) ? sm[t - off] : 0;
        __syncthreads();
        sm[t] += x;
        __syncthreads();
    }
    if (t < NSB) g_boff[t] = sm[t] - v;
}

__global__ void __launch_bounds__(SBLK) k_scan3() {
    int i = blockIdx.x * SBLK + threadIdx.x;
    if (i >= M) return;
    int val = g_rowstart[i] + g_boff[i >> 10];
    g_rowstart[i] = val;
    g_cursor[i]   = val;
    int c = g_cnt[i];
    g_rinv[i] = 1.0f / (float)(c > 0 ? c : 1);
}

// ---------------------------------------------------------------------------
// Fill: bucket edges by (dst, rel) into packed records (src | t<<20).
// ---------------------------------------------------------------------------
__global__ void k_fill(const void* ei, const void* et) {
    int e = blockIdx.x * blockDim.x + threadIdx.x;
    if (e >= E) return;
    int is64 = g_is64;
    int src = (int)ldidx(ei, e, is64);
    int dst = (int)ldidx(ei, (long long)E + e, is64);
    int t   = (int)ldidx(et, e, is64);
    int pos = atomicAdd(&g_cursor[dst * NREL + t], 1);
    g_erec[pos] = (unsigned)src | ((unsigned)t << 20);
}

// ---------------------------------------------------------------------------
// Persistent-W, double-buffered-X transform GEMM (tf32 tensor cores).
//   grid = (GEMM_BX, 9). Block (bx, ct) keeps W[ct] in smem (tf32) for its
//   whole life and strides over row-tiles bx, bx+GEMM_BX, ... For each tile
//   it cp.async-prefetches the NEXT X tile (raw fp32, embedding gather
//   hitting the L2-resident 179 KB emb table) while running MMAs on the
//   current one. X is converted to tf32 at fragment-load time.
//   ct<8 -> xr[ct] = bf16(feat @ w_rel[ct]);  ct=8 -> agg = feat@w_root+bias
// ---------------------------------------------------------------------------
__device__ __forceinline__ unsigned f2tf32(float v) {
    unsigned u;
    asm("cvt.rna.tf32.f32 %0, %1;" : "=r"(u) : "f"(v));
    return u;
}
__device__ __forceinline__ void cp16(unsigned smem_addr, const void* gptr) {
    asm volatile("cp.async.cg.shared.global [%0], [%1], 16;\n"
                 :: "r"(smem_addr), "l"(gptr));
}
__device__ __forceinline__ void cp_commit() {
    asm volatile("cp.async.commit_group;\n");
}
template <int NN>
__device__ __forceinline__ void cp_wait() {
    asm volatile("cp.async.wait_group %0;\n" :: "n"(NN));
}

static constexpr int LDX = 132;  // padded row stride (floats)

__global__ void __launch_bounds__(256) k_gemm(
    const void* x, const float* emb, const float* wrel,
    const float* wroot, const float* bias)
{
    extern __shared__ float smem[];
    float* Ws = smem;                    // [128][132] tf32 (k-major: Ws[k][n])
    float* Xb[2] = { smem + 128 * LDX, smem + 2 * 128 * LDX };  // raw fp32
    __shared__ int idxs[2][128];

    const int tid  = threadIdx.x;
    const int ct   = blockIdx.y;
    const int is64 = g_is64;

    // --- Load W once, pre-converted to tf32 ---
    const float* W = (ct < 8) ? (wrel + (size_t)ct * D * D) : wroot;
    for (int i = tid; i < 128 * 128; i += 256) {
        int r = i >> 7, c = i & 127;
        Ws[r * LDX + c] = __uint_as_float(f2tf32(W[i]));
    }

    const int warp = tid >> 5, lane = tid & 31;
    const int wrow = (warp >> 1) * 32;
    const int wcol = (warp & 1) * 64;
    const int lg = lane >> 2;
    const int lt = lane & 3;

    const unsigned xb_addr[2] = {
        (unsigned)__cvta_generic_to_shared(Xb[0]),
        (unsigned)__cvta_generic_to_shared(Xb[1]) };

    // --- Prologue: idxs + cp.async for first tile ---
    int tile0 = blockIdx.x;
    if (tid < 128) {
        int n = tile0 * 128 + tid;
        idxs[0][tid] = (n < N) ? (int)ldidx(x, n, is64) : 0;
    }
    __syncthreads();   // idxs[0] ready (also covers Ws for later reads)
    // 4096 16B chunks: chunk c -> row c>>5, 16B-slot c&31
    for (int c = tid; c < 4096; c += 256) {
        int r = c >> 5, s = c & 31;
        cp16(xb_addr[0] + (unsigned)(r * LDX * 4 + s * 16),
             emb + (size_t)idxs[0][r] * D + s * 4);
    }
    cp_commit();

    for (int tile = tile0, it = 0; tile < ROWTILES; tile += GEMM_BX, it++) {
        const int cur = it & 1, nxt = cur ^ 1;
        const int tnext = tile + GEMM_BX;

        // Stage next tile's indices
        if (tnext < ROWTILES && tid < 128) {
            int n = tnext * 128 + tid;
            idxs[nxt][tid] = (n < N) ? (int)ldidx(x, n, is64) : 0;
        }
        __syncthreads();  // idxs[nxt] ready; prev compute done reading Xb[nxt]

        // Issue next tile's gather while we compute on the current one
        if (tnext < ROWTILES) {
            for (int c = tid; c < 4096; c += 256) {
                int r = c >> 5, s = c & 31;
                cp16(xb_addr[nxt] + (unsigned)(r * LDX * 4 + s * 16),
                     emb + (size_t)idxs[nxt][r] * D + s * 4);
            }
            cp_commit();
            cp_wait<1>();   // current tile's group complete
        } else {
            cp_wait<0>();
        }
        __syncthreads();    // all threads see Xb[cur]

        const float* Xs = Xb[cur];

        float c_[2][8][4];
        #pragma unroll
        for (int mi = 0; mi < 2; mi++)
            #pragma unroll
            for (int ni = 0; ni < 8; ni++)
                #pragma unroll
                for (int q = 0; q < 4; q++) c_[mi][ni][q] = 0.0f;

        const unsigned* Wu = reinterpret_cast<const unsigned*>(Ws);

        #pragma unroll 4
        for (int k0 = 0; k0 < 128; k0 += 8) {
            unsigned a[2][4], b[8][2];
            #pragma unroll
            for (int mi = 0; mi < 2; mi++) {
                int r0 = wrow + mi * 16 + lg;
                int cc = k0 + lt;
                a[mi][0] = f2tf32(Xs[r0 * LDX + cc]);
                a[mi][1] = f2tf32(Xs[(r0 + 8) * LDX + cc]);
                a[mi][2] = f2tf32(Xs[r0 * LDX + cc + 4]);
                a[mi][3] = f2tf32(Xs[(r0 + 8) * LDX + cc + 4]);
            }
            #pragma unroll
            for (int ni = 0; ni < 8; ni++) {
                int col = wcol + ni * 8 + lg;
                int kk = k0 + lt;
                b[ni][0] = Wu[kk * LDX + col];
                b[ni][1] = Wu[(kk + 4) * LDX + col];
            }
            #pragma unroll
            for (int mi = 0; mi < 2; mi++) {
                #pragma unroll
                for (int ni = 0; ni < 8; ni++) {
                    asm volatile(
                        "mma.sync.aligned.m16n8k8.row.col.f32.tf32.tf32.f32 "
                        "{%0,%1,%2,%3}, {%4,%5,%6,%7}, {%8,%9}, {%0,%1,%2,%3};"
                        : "+f"(c_[mi][ni][0]), "+f"(c_[mi][ni][1]),
                          "+f"(c_[mi][ni][2]), "+f"(c_[mi][ni][3])
                        : "r"(a[mi][0]), "r"(a[mi][1]), "r"(a[mi][2]), "r"(a[mi][3]),
                          "r"(b[ni][0]), "r"(b[ni][1]));
                }
            }
        }

        // Epilogue (rows padded to NPAD; pad rows never read downstream)
        const int rb = tile * 128;
        #pragma unroll
        for (int mi = 0; mi < 2; mi++) {
            #pragma unroll
            for (int ni = 0; ni < 8; ni++) {
                int row = rb + wrow + mi * 16 + lg;
                int col = wcol + ni * 8 + 2 * lt;
                float c0 = c_[mi][ni][0], c1 = c_[mi][ni][1];
                float c2 = c_[mi][ni][2], c3 = c_[mi][ni][3];
                if (ct < 8) {
                    __nv_bfloat16* base = g_xr + ((size_t)ct * NPAD + row) * D;
                    *(__nv_bfloat162*)(base + col) =
                        __float22bfloat162_rn(make_float2(c0, c1));
                    *(__nv_bfloat162*)(base + 8 * D + col) =
                        __float22bfloat162_rn(make_float2(c2, c3));
                } else {
                    float* base = g_agg + (size_t)row * D;
                    float b0 = bias[col], b1 = bias[col + 1];
                    *(float2*)(base + col)         = make_float2(c0 + b0, c1 + b1);
                    *(float2*)(base + 8 * D + col) = make_float2(c2 + b0, c3 + b1);
                }
            }
        }
    }
}

// ---------------------------------------------------------------------------
// Pull-aggregation + fused pool. One warp per dst node:
//   h = relu( seed[dst] + sum_{e in CSR(dst)} xr[t_e][src_e] * rinv(dst,t_e) )
//   if node_type[dst]==0: segsum[batch[dst]] += h; segcnt += 1
// Inner loop batched 4-wide: 4 independent 256B row gathers in flight per
// warp (MLP=4) with a short scalar tail. Trip counts are warp-uniform.
// Reciprocals precomputed in k_scan3 (no I2F/MUFU on critical path).
// ---------------------------------------------------------------------------
__global__ void __launch_bounds__(256) k_aggpool(const void* batch, const void* ntype) {
    const int lane = threadIdx.x & 31;
    const int dst  = blockIdx.x * 8 + (threadIdx.x >> 5);
    if (dst >= N) return;
    const int is64 = g_is64;
    const int key0 = dst * NREL;

    const int s   = g_rowstart[key0];
    const int epd = (key0 + NREL < M) ? g_rowstart[key0 + NREL] : E;

    float a0 = 0.0f, a1 = 0.0f, a2 = 0.0f, a3 = 0.0f;

    int i = s;
    // 4-wide batched main loop
    for (; i + 4 <= epd; i += 4) {
        unsigned rec0 = g_erec[i + 0];
        unsigned rec1 = g_erec[i + 1];
        unsigned rec2 = g_erec[i + 2];
        unsigned rec3 = g_erec[i + 3];
        int t0 = rec0 >> 20, t1 = rec1 >> 20, t2 = rec2 >> 20, t3 = rec3 >> 20;
        float v0 = g_rinv[key0 + t0];
        float v1 = g_rinv[key0 + t1];
        float v2 = g_rinv[key0 + t2];
        float v3 = g_rinv[key0 + t3];
        uint2 r0 = ((const uint2*)(g_xr + ((size_t)t0 * NPAD + (rec0 & 0xFFFFF)) * D))[lane];
        uint2 r1 = ((const uint2*)(g_xr + ((size_t)t1 * NPAD + (rec1 & 0xFFFFF)) * D))[lane];
        uint2 r2 = ((const uint2*)(g_xr + ((size_t)t2 * NPAD + (rec2 & 0xFFFFF)) * D))[lane];
        uint2 r3 = ((const uint2*)(g_xr + ((size_t)t3 * NPAD + (rec3 & 0xFFFFF)) * D))[lane];
        float2 f;
        f = __bfloat1622float2(*(__nv_bfloat162*)&r0.x); a0 = fmaf(f.x, v0, a0); a1 = fmaf(f.y, v0, a1);
        f = __bfloat1622float2(*(__nv_bfloat162*)&r0.y); a2 = fmaf(f.x, v0, a2); a3 = fmaf(f.y, v0, a3);
        f = __bfloat1622float2(*(__nv_bfloat162*)&r1.x); a0 = fmaf(f.x, v1, a0); a1 = fmaf(f.y, v1, a1);
        f = __bfloat1622float2(*(__nv_bfloat162*)&r1.y); a2 = fmaf(f.x, v1, a2); a3 = fmaf(f.y, v1, a3);
        f = __bfloat1622float2(*(__nv_bfloat162*)&r2.x); a0 = fmaf(f.x, v2, a0); a1 = fmaf(f.y, v2, a1);
        f = __bfloat1622float2(*(__nv_bfloat162*)&r2.y); a2 = fmaf(f.x, v2, a2); a3 = fmaf(f.y, v2, a3);
        f = __bfloat1622float2(*(__nv_bfloat162*)&r3.x); a0 = fmaf(f.x, v3, a0); a1 = fmaf(f.y, v3, a1);
        f = __bfloat1622float2(*(__nv_bfloat162*)&r3.y); a2 = fmaf(f.x, v3, a2); a3 = fmaf(f.y, v3, a3);
    }
    // scalar tail (<= 3 iterations)
    for (; i < epd; i++) {
        unsigned rec = g_erec[i];
        int t = rec >> 20;
        float inv = g_rinv[key0 + t];
        uint2 rv = ((const uint2*)(g_xr + ((size_t)t * NPAD + (rec & 0xFFFFF)) * D))[lane];
        float2 f0 = __bfloat1622float2(*(__nv_bfloat162*)&rv.x);
        float2 f1 = __bfloat1622float2(*(__nv_bfloat162*)&rv.y);
        a0 = fmaf(f0.x, inv, a0);
        a1 = fmaf(f0.y, inv, a1);
        a2 = fmaf(f1.x, inv, a2);
        a3 = fmaf(f1.y, inv, a3);
    }

    float4 seed = *(const float4*)(g_agg + (size_t)dst * D + lane * 4);
    float h0 = fmaxf(a0 + seed.x, 0.0f);
    float h1 = fmaxf(a1 + seed.y, 0.0f);
    float h2 = fmaxf(a2 + seed.z, 0.0f);
    float h3 = fmaxf(a3 + seed.w, 0.0f);

    long long nt = ldidx(ntype, dst, is64);
    if (nt == 0) {
        long long g = ldidx(batch, dst, is64);
        float* dp = g_segsum + (int)g * D + lane * 4;
        asm volatile("red.global.add.v4.f32 [%0], {%1,%2,%3,%4};"
                     :: "l"(dp), "f"(h0), "f"(h1), "f"(h2), "f"(h3)
                     : "memory");
        if (lane == 0) atomicAdd(&g_segcnt[(int)g], 1.0f);
    }
}

// ---------------------------------------------------------------------------
// Final: out[g] = (segsum[g]/max(cnt,1)) @ lin_w^T + lin_b
// ---------------------------------------------------------------------------
__global__ void __launch_bounds__(128) k_final(const float* linw, const float* linb,
                                               float* out) {
    __shared__ float gv[D];
    const int g = blockIdx.x, tid = threadIdx.x;
    float cnt = g_segcnt[g];
    float inv = 1.0f / fmaxf(cnt, 1.0f);
    gv[tid] = g_segsum[g * D + tid] * inv;
    __syncthreads();
    if (tid < NC) {
        float s = linb[tid];
        const float* w = linw + tid * D;
        #pragma unroll 8
        for (int h = 0; h < D; h++) s += gv[h] * w[h];
        out[g * NC + tid] = s;
    }
}

// ---------------------------------------------------------------------------
extern "C" void kernel_launch(void* const* d_in, const int* in_sizes, int n_in,
                              void* d_out, int out_size) {
    // Input order: x, edge_index, edge_type, batch, node_type,
    //              [num_graphs scalar], node_emb_w, w_root, w_rel,
    //              conv_bias, lin_w, lin_b
    int off = (n_in >= 12) ? 1 : 0;
    const void* x     = d_in[0];
    const void* ei    = d_in[1];
    const void* et    = d_in[2];
    const void* batch = d_in[3];
    const void* ntype = d_in[4];
    const float* emb   = (const float*)d_in[5 + off];
    const float* wroot = (const float*)d_in[6 + off];
    const float* wrel  = (const float*)d_in[7 + off];
    const float* bias  = (const float*)d_in[8 + off];
    const float* linw  = (const float*)d_in[9 + off];
    const float* linb  = (const float*)d_in[10 + off];
    float* out = (float*)d_out;

    // W (tf32) + 2 X buffers (raw fp32), 128x132 each
    const int smem_bytes = 3 * 128 * LDX * (int)sizeof(float);  // 202752
    cudaFuncSetAttribute(k_gemm, cudaFuncAttributeMaxDynamicSharedMemorySize,
                         smem_bytes);

    k_zero<<<(M + 255) / 256, 256>>>((const unsigned*)ei);
    k_gemm<<<dim3(GEMM_BX, 9), 256, smem_bytes>>>(x, emb, wrel, wroot, bias);
    k_count<<<(E + 255) / 256, 256>>>(ei, et);
    k_scan1<<<NSB, SBLK>>>();
    k_scan2<<<1, SBLK>>>();
    k_scan3<<<NSB, SBLK>>>();
    k_fill<<<(E + 255) / 256, 256>>>(ei, et);
    k_aggpool<<<(N + 7) / 8, 256>>>(batch, ntype);
    k_final<<<G, 128>>>(linw, linb, out);
}

// round 15
// speedup vs baseline: 1.3288x; 1.3288x over previous
#include <cuda_runtime.h>
#include <cuda_bf16.h>
#include <cstdint>
#include <cstddef>

// Problem constants
static constexpr int N     = 100000;   // nodes
static constexpr int NPAD  = 100096;   // padded to 782*128
static constexpr int E     = 1600000;  // edges
static constexpr int NREL  = 8;
static constexpr int D     = 128;      // embed == hidden
static constexpr int G     = 64;       // graphs
static constexpr int NC    = 49;       // output classes
static constexpr int ROWTILES = NPAD / 128;  // 782
static constexpr int M     = N * NREL;       // 800000 (dst,rel) buckets
static constexpr int SBLK  = 1024;           // scan block size
static constexpr int NSB   = (M + SBLK - 1) / SBLK;  // 782 scan blocks
static constexpr int GEMM_BX = 16;           // persistent blocks per ct (16*9=144 <= 148)

// Scratch (static device globals; no runtime allocation)
__device__ __nv_bfloat16 g_xr[(size_t)NREL * NPAD * D]; // 205 MB messages (bf16)
__device__ float    g_agg[(size_t)NPAD * D];   // 51 MB: root@w + bias seed
__device__ int      g_cnt[M];                  // per (dst,rel) in-degree
__device__ float    g_rinv[M];                 // 1/max(cnt,1) precomputed
__device__ int      g_rowstart[M];             // CSR starts (exclusive scan of cnt)
__device__ int      g_cursor[M];               // fill cursors
__device__ int      g_bsum[NSB];               // scan partials
__device__ int      g_boff[NSB];               // scanned partials
__device__ unsigned g_erec[E];                 // packed (src | t<<20), bucketed
__device__ float    g_segsum[G * D];
__device__ float    g_segcnt[G];
__device__ int      g_is64;

// ---------------------------------------------------------------------------
// int64-vs-int32 index helper (decided at runtime by detector in k_zero)
// ---------------------------------------------------------------------------
__device__ __forceinline__ long long ldidx(const void* p, long long i, int is64) {
    if (is64) return ((const long long*)p)[i];
    return (long long)((const int*)p)[i];
}

// ---------------------------------------------------------------------------
// Zero accumulators + int64 detection (fused; one launch).
// ---------------------------------------------------------------------------
__global__ void k_zero(const unsigned* ei_words) {
    int i = blockIdx.x * blockDim.x + threadIdx.x;
    if (i < M)     g_cnt[i] = 0;
    if (i < G * D) g_segsum[i] = 0.0f;
    if (i < G)     g_segcnt[i] = 0.0f;
    if (i == 0) {
        int is64 = 1;
        for (int k = 0; k < 64; k++) {
            if (ei_words[2 * k + 1] != 0u) { is64 = 0; break; }
        }
        g_is64 = is64;
    }
}

// ---------------------------------------------------------------------------
// Histogram: in-degree per (dst, rel)
// ---------------------------------------------------------------------------
__global__ void k_count(const void* ei, const void* et) {
    int e = blockIdx.x * blockDim.x + threadIdx.x;
    if (e >= E) return;
    int is64 = g_is64;
    int dst = (int)ldidx(ei, (long long)E + e, is64);
    int t   = (int)ldidx(et, e, is64);
    atomicAdd(&g_cnt[dst * NREL + t], 1);
}

// ---------------------------------------------------------------------------
// Exclusive scan of g_cnt (3 kernels). Produces g_rowstart, inits g_cursor,
// and precomputes g_rinv = 1/max(cnt,1).
// ---------------------------------------------------------------------------
__global__ void __launch_bounds__(SBLK) k_scan1() {
    __shared__ int sm[SBLK];
    int t = threadIdx.x;
    int i = blockIdx.x * SBLK + t;
    int v = (i < M) ? g_cnt[i] : 0;
    sm[t] = v;
    __syncthreads();
    #pragma unroll
    for (int off = 1; off < SBLK; off <<= 1) {
        int x = (t >= off) ? sm[t - off] : 0;
        __syncthreads();
        sm[t] += x;
        __syncthreads();
    }
    if (i < M) g_rowstart[i] = sm[t] - v;
    if (t == SBLK - 1) g_bsum[blockIdx.x] = sm[t];
}

__global__ void __launch_bounds__(SBLK) k_scan2() {
    __shared__ int sm[SBLK];
    int t = threadIdx.x;
    int v = (t < NSB) ? g_bsum[t] : 0;
    sm[t] = v;
    __syncthreads();
    #pragma unroll
    for (int off = 1; off < SBLK; off <<= 1) {
        int x = (t >= off) ? sm[t - off] : 0;
        __syncthreads();
        sm[t] += x;
        __syncthreads();
    }
    if (t < NSB) g_boff[t] = sm[t] - v;
}

__global__ void __launch_bounds__(SBLK) k_scan3() {
    int i = blockIdx.x * SBLK + threadIdx.x;
    if (i >= M) return;
    int val = g_rowstart[i] + g_boff[i >> 10];
    g_rowstart[i] = val;
    g_cursor[i]   = val;
    int c = g_cnt[i];
    g_rinv[i] = 1.0f / (float)(c > 0 ? c : 1);
}

// ---------------------------------------------------------------------------
// Fill: bucket edges by (dst, rel) into packed records (src | t<<20).
// ---------------------------------------------------------------------------
__global__ void k_fill(const void* ei, const void* et) {
    int e = blockIdx.x * blockDim.x + threadIdx.x;
    if (e >= E) return;
    int is64 = g_is64;
    int src = (int)ldidx(ei, e, is64);
    int dst = (int)ldidx(ei, (long long)E + e, is64);
    int t   = (int)ldidx(et, e, is64);
    int pos = atomicAdd(&g_cursor[dst * NREL + t], 1);
    g_erec[pos] = (unsigned)src | ((unsigned)t << 20);
}

// ---------------------------------------------------------------------------
// Persistent-W, double-buffered-X transform GEMM — bf16 m16n8k16 MMA.
//   grid = (GEMM_BX, 9). Block (bx, ct) pre-packs W[ct] into bf16x2 pairs
//   (k-paired, [n][kp] layout) once, then strides over row-tiles. X tiles
//   are cp.async-prefetched as raw fp32 (emb gather, L2-resident table) and
//   packed to bf16x2 at fragment-load time. fp32 accumulate.
//   ct<8 -> xr[ct] = bf16(feat @ w_rel[ct]);  ct=8 -> agg = feat@w_root+bias
// ---------------------------------------------------------------------------
__device__ __forceinline__ void cp16(unsigned smem_addr, const void* gptr) {
    asm volatile("cp.async.cg.shared.global [%0], [%1], 16;\n"
                 :: "r"(smem_addr), "l"(gptr));
}
__device__ __forceinline__ void cp_commit() {
    asm volatile("cp.async.commit_group;\n");
}
template <int NN>
__device__ __forceinline__ void cp_wait() {
    asm volatile("cp.async.wait_group %0;\n" :: "n"(NN));
}
__device__ __forceinline__ unsigned packbf2(float lo, float hi) {
    __nv_bfloat162 p = __float22bfloat162_rn(make_float2(lo, hi));
    return *(unsigned*)&p;
}

static constexpr int LDX = 132;  // padded X row stride (floats)
static constexpr int WST = 68;   // padded Wb row stride (bf16x2 words)

__global__ void __launch_bounds__(256) k_gemm(
    const void* x, const float* emb, const float* wrel,
    const float* wroot, const float* bias)
{
    extern __shared__ float smem[];
    unsigned* Wb = (unsigned*)smem;                       // [128][68] bf16x2: Wb[n][kp]
    float* Xb[2] = { smem + 8704, smem + 8704 + 128 * LDX };  // raw fp32 tiles
    __shared__ int idxs[2][128];

    const int tid  = threadIdx.x;
    const int ct   = blockIdx.y;
    const int is64 = g_is64;

    // --- Pack W once: Wb[n][kp] = bf16x2(W[2kp][n], W[2kp+1][n]) ---
    const float* W = (ct < 8) ? (wrel + (size_t)ct * D * D) : wroot;
    for (int i = tid; i < 128 * 64; i += 256) {
        int n  = i & 127;          // fast: coalesced gmem row reads
        int kp = i >> 7;
        float lo = W[(2 * kp) * D + n];
        float hi = W[(2 * kp + 1) * D + n];
        Wb[n * WST + kp] = packbf2(lo, hi);
    }

    const int warp = tid >> 5, lane = tid & 31;
    const int wrow = (warp >> 1) * 32;   // 4 warps along M
    const int wcol = (warp & 1) * 64;    // 2 warps along N
    const int lg = lane >> 2;            // 0..7
    const int lt = lane & 3;             // 0..3

    const unsigned xb_addr[2] = {
        (unsigned)__cvta_generic_to_shared(Xb[0]),
        (unsigned)__cvta_generic_to_shared(Xb[1]) };

    // --- Prologue: idxs + cp.async for first tile ---
    int tile0 = blockIdx.x;
    if (tid < 128) {
        int n = tile0 * 128 + tid;
        idxs[0][tid] = (n < N) ? (int)ldidx(x, n, is64) : 0;
    }
    __syncthreads();   // idxs[0] ready
    for (int c = tid; c < 4096; c += 256) {
        int r = c >> 5, s = c & 31;
        cp16(xb_addr[0] + (unsigned)(r * LDX * 4 + s * 16),
             emb + (size_t)idxs[0][r] * D + s * 4);
    }
    cp_commit();

    for (int tile = tile0, it = 0; tile < ROWTILES; tile += GEMM_BX, it++) {
        const int cur = it & 1, nxt = cur ^ 1;
        const int tnext = tile + GEMM_BX;

        if (tnext < ROWTILES && tid < 128) {
            int n = tnext * 128 + tid;
            idxs[nxt][tid] = (n < N) ? (int)ldidx(x, n, is64) : 0;
        }
        __syncthreads();  // idxs[nxt] ready; prev compute done with Xb[nxt]; Wb ready

        if (tnext < ROWTILES) {
            for (int c = tid; c < 4096; c += 256) {
                int r = c >> 5, s = c & 31;
                cp16(xb_addr[nxt] + (unsigned)(r * LDX * 4 + s * 16),
                     emb + (size_t)idxs[nxt][r] * D + s * 4);
            }
            cp_commit();
            cp_wait<1>();   // current tile's group complete
        } else {
            cp_wait<0>();
        }
        __syncthreads();

        const float* Xs = Xb[cur];

        float c_[2][8][4];
        #pragma unroll
        for (int mi = 0; mi < 2; mi++)
            #pragma unroll
            for (int ni = 0; ni < 8; ni++)
                #pragma unroll
                for (int q = 0; q < 4; q++) c_[mi][ni][q] = 0.0f;

        // 8 K-steps of 16 (bf16 m16n8k16)
        #pragma unroll
        for (int k0 = 0; k0 < 128; k0 += 16) {
            unsigned a[2][4], b[8][2];
            const int kp0 = k0 >> 1;
            #pragma unroll
            for (int mi = 0; mi < 2; mi++) {
                int r0 = wrow + mi * 16 + lg;
                const float* x0 = Xs + r0 * LDX + k0 + 2 * lt;
                const float* x1 = Xs + (r0 + 8) * LDX + k0 + 2 * lt;
                float2 f00 = *(const float2*)(x0);
                float2 f10 = *(const float2*)(x1);
                float2 f01 = *(const float2*)(x0 + 8);
                float2 f11 = *(const float2*)(x1 + 8);
                a[mi][0] = packbf2(f00.x, f00.y);
                a[mi][1] = packbf2(f10.x, f10.y);
                a[mi][2] = packbf2(f01.x, f01.y);
                a[mi][3] = packbf2(f11.x, f11.y);
            }
            #pragma unroll
            for (int ni = 0; ni < 8; ni++) {
                int col = wcol + ni * 8 + lg;
                b[ni][0] = Wb[col * WST + kp0 + lt];
                b[ni][1] = Wb[col * WST + kp0 + lt + 4];
            }
            #pragma unroll
            for (int mi = 0; mi < 2; mi++) {
                #pragma unroll
                for (int ni = 0; ni < 8; ni++) {
                    asm volatile(
                        "mma.sync.aligned.m16n8k16.row.col.f32.bf16.bf16.f32 "
                        "{%0,%1,%2,%3}, {%4,%5,%6,%7}, {%8,%9}, {%0,%1,%2,%3};"
                        : "+f"(c_[mi][ni][0]), "+f"(c_[mi][ni][1]),
                          "+f"(c_[mi][ni][2]), "+f"(c_[mi][ni][3])
                        : "r"(a[mi][0]), "r"(a[mi][1]), "r"(a[mi][2]), "r"(a[mi][3]),
                          "r"(b[ni][0]), "r"(b[ni][1]));
                }
            }
        }

        // Epilogue (D layout identical to m16n8k8; rows padded to NPAD)
        const int rb = tile * 128;
        #pragma unroll
        for (int mi = 0; mi < 2; mi++) {
            #pragma unroll
            for (int ni = 0; ni < 8; ni++) {
                int row = rb + wrow + mi * 16 + lg;
                int col = wcol + ni * 8 + 2 * lt;
                float c0 = c_[mi][ni][0], c1 = c_[mi][ni][1];
                float c2 = c_[mi][ni][2], c3 = c_[mi][ni][3];
                if (ct < 8) {
                    __nv_bfloat16* base = g_xr + ((size_t)ct * NPAD + row) * D;
                    *(__nv_bfloat162*)(base + col) =
                        __float22bfloat162_rn(make_float2(c0, c1));
                    *(__nv_bfloat162*)(base + 8 * D + col) =
                        __float22bfloat162_rn(make_float2(c2, c3));
                } else {
                    float* base = g_agg + (size_t)row * D;
                    float b0 = bias[col], b1 = bias[col + 1];
                    *(float2*)(base + col)         = make_float2(c0 + b0, c1 + b1);
                    *(float2*)(base + 8 * D + col) = make_float2(c2 + b0, c3 + b1);
                }
            }
        }
    }
}

// ---------------------------------------------------------------------------
// Pull-aggregation + fused pool. One warp per dst node; MLP=4 batched loop.
// ---------------------------------------------------------------------------
__global__ void __launch_bounds__(256) k_aggpool(const void* batch, const void* ntype) {
    const int lane = threadIdx.x & 31;
    const int dst  = blockIdx.x * 8 + (threadIdx.x >> 5);
    if (dst >= N) return;
    const int is64 = g_is64;
    const int key0 = dst * NREL;

    const int s   = g_rowstart[key0];
    const int epd = (key0 + NREL < M) ? g_rowstart[key0 + NREL] : E;

    float a0 = 0.0f, a1 = 0.0f, a2 = 0.0f, a3 = 0.0f;

    int i = s;
    for (; i + 4 <= epd; i += 4) {
        unsigned rec0 = g_erec[i + 0];
        unsigned rec1 = g_erec[i + 1];
        unsigned rec2 = g_erec[i + 2];
        unsigned rec3 = g_erec[i + 3];
        int t0 = rec0 >> 20, t1 = rec1 >> 20, t2 = rec2 >> 20, t3 = rec3 >> 20;
        float v0 = g_rinv[key0 + t0];
        float v1 = g_rinv[key0 + t1];
        float v2 = g_rinv[key0 + t2];
        float v3 = g_rinv[key0 + t3];
        uint2 r0 = ((const uint2*)(g_xr + ((size_t)t0 * NPAD + (rec0 & 0xFFFFF)) * D))[lane];
        uint2 r1 = ((const uint2*)(g_xr + ((size_t)t1 * NPAD + (rec1 & 0xFFFFF)) * D))[lane];
        uint2 r2 = ((const uint2*)(g_xr + ((size_t)t2 * NPAD + (rec2 & 0xFFFFF)) * D))[lane];
        uint2 r3 = ((const uint2*)(g_xr + ((size_t)t3 * NPAD + (rec3 & 0xFFFFF)) * D))[lane];
        float2 f;
        f = __bfloat1622float2(*(__nv_bfloat162*)&r0.x); a0 = fmaf(f.x, v0, a0); a1 = fmaf(f.y, v0, a1);
        f = __bfloat1622float2(*(__nv_bfloat162*)&r0.y); a2 = fmaf(f.x, v0, a2); a3 = fmaf(f.y, v0, a3);
        f = __bfloat1622float2(*(__nv_bfloat162*)&r1.x); a0 = fmaf(f.x, v1, a0); a1 = fmaf(f.y, v1, a1);
        f = __bfloat1622float2(*(__nv_bfloat162*)&r1.y); a2 = fmaf(f.x, v1, a2); a3 = fmaf(f.y, v1, a3);
        f = __bfloat1622float2(*(__nv_bfloat162*)&r2.x); a0 = fmaf(f.x, v2, a0); a1 = fmaf(f.y, v2, a1);
        f = __bfloat1622float2(*(__nv_bfloat162*)&r2.y); a2 = fmaf(f.x, v2, a2); a3 = fmaf(f.y, v2, a3);
        f = __bfloat1622float2(*(__nv_bfloat162*)&r3.x); a0 = fmaf(f.x, v3, a0); a1 = fmaf(f.y, v3, a1);
        f = __bfloat1622float2(*(__nv_bfloat162*)&r3.y); a2 = fmaf(f.x, v3, a2); a3 = fmaf(f.y, v3, a3);
    }
    for (; i < epd; i++) {
        unsigned rec = g_erec[i];
        int t = rec >> 20;
        float inv = g_rinv[key0 + t];
        uint2 rv = ((const uint2*)(g_xr + ((size_t)t * NPAD + (rec & 0xFFFFF)) * D))[lane];
        float2 f0 = __bfloat1622float2(*(__nv_bfloat162*)&rv.x);
        float2 f1 = __bfloat1622float2(*(__nv_bfloat162*)&rv.y);
        a0 = fmaf(f0.x, inv, a0);
        a1 = fmaf(f0.y, inv, a1);
        a2 = fmaf(f1.x, inv, a2);
        a3 = fmaf(f1.y, inv, a3);
    }

    float4 seed = *(const float4*)(g_agg + (size_t)dst * D + lane * 4);
    float h0 = fmaxf(a0 + seed.x, 0.0f);
    float h1 = fmaxf(a1 + seed.y, 0.0f);
    float h2 = fmaxf(a2 + seed.z, 0.0f);
    float h3 = fmaxf(a3 + seed.w, 0.0f);

    long long nt = ldidx(ntype, dst, is64);
    if (nt == 0) {
        long long g = ldidx(batch, dst, is64);
        float* dp = g_segsum + (int)g * D + lane * 4;
        asm volatile("red.global.add.v4.f32 [%0], {%1,%2,%3,%4};"
                     :: "l"(dp), "f"(h0), "f"(h1), "f"(h2), "f"(h3)
                     : "memory");
        if (lane == 0) atomicAdd(&g_segcnt[(int)g], 1.0f);
    }
}

// ---------------------------------------------------------------------------
// Final: out[g] = (segsum[g]/max(cnt,1)) @ lin_w^T + lin_b
// ---------------------------------------------------------------------------
__global__ void __launch_bounds__(128) k_final(const float* linw, const float* linb,
                                               float* out) {
    __shared__ float gv[D];
    const int g = blockIdx.x, tid = threadIdx.x;
    float cnt = g_segcnt[g];
    float inv = 1.0f / fmaxf(cnt, 1.0f);
    gv[tid] = g_segsum[g * D + tid] * inv;
    __syncthreads();
    if (tid < NC) {
        float s = linb[tid];
        const float* w = linw + tid * D;
        #pragma unroll 8
        for (int h = 0; h < D; h++) s += gv[h] * w[h];
        out[g * NC + tid] = s;
    }
}

// ---------------------------------------------------------------------------
extern "C" void kernel_launch(void* const* d_in, const int* in_sizes, int n_in,
                              void* d_out, int out_size) {
    // Input order: x, edge_index, edge_type, batch, node_type,
    //              [num_graphs scalar], node_emb_w, w_root, w_rel,
    //              conv_bias, lin_w, lin_b
    int off = (n_in >= 12) ? 1 : 0;
    const void* x     = d_in[0];
    const void* ei    = d_in[1];
    const void* et    = d_in[2];
    const void* batch = d_in[3];
    const void* ntype = d_in[4];
    const float* emb   = (const float*)d_in[5 + off];
    const float* wroot = (const float*)d_in[6 + off];
    const float* wrel  = (const float*)d_in[7 + off];
    const float* bias  = (const float*)d_in[8 + off];
    const float* linw  = (const float*)d_in[9 + off];
    const float* linb  = (const float*)d_in[10 + off];
    float* out = (float*)d_out;

    // Wb (bf16x2, 128*68 words) + 2 X buffers (fp32 128x132)
    const int smem_bytes = (8704 + 2 * 128 * LDX) * (int)sizeof(float);  // 169984
    cudaFuncSetAttribute(k_gemm, cudaFuncAttributeMaxDynamicSharedMemorySize,
                         smem_bytes);

    k_zero<<<(M + 255) / 256, 256>>>((const unsigned*)ei);
    k_gemm<<<dim3(GEMM_BX, 9), 256, smem_bytes>>>(x, emb, wrel, wroot, bias);
    k_count<<<(E + 255) / 256, 256>>>(ei, et);
    k_scan1<<<NSB, SBLK>>>();
    k_scan2<<<1, SBLK>>>();
    k_scan3<<<NSB, SBLK>>>();
    k_fill<<<(E + 255) / 256, 256>>>(ei, et);
    k_aggpool<<<(N + 7) / 8, 256>>>(batch, ntype);
    k_final<<<G, 128>>>(linw, linb, out);
}

// round 16
// speedup vs baseline: 3.6155x; 2.7209x over previous
#include <cuda_runtime.h>
#include <cuda_bf16.h>
#include <cstdint>
#include <cstddef>

// Problem constants
static constexpr int N     = 100000;   // nodes
static constexpr int E     = 1600000;  // edges
static constexpr int NREL  = 8;
static constexpr int NTYPE = 250;      // distinct embedding rows (events+entities)
static constexpr int TPAD  = 256;      // padded type count
static constexpr int D     = 128;      // embed == hidden
static constexpr int G     = 64;       // graphs
static constexpr int NC    = 49;       // output classes
static constexpr int M     = N * NREL; // 800000 (dst,rel) buckets
static constexpr int SBLK  = 1024;     // scan block size
static constexpr int NSB   = (M + SBLK - 1) / SBLK;  // 782 scan blocks

// Scratch (static device globals; no runtime allocation)
__device__ __nv_bfloat16 g_xrt[NREL * TPAD * D];  // 512 KB: per-(rel,type) messages
__device__ float    g_root[TPAD * D];             // 128 KB: emb@w_root + bias per type
__device__ int      g_cnt[M];                     // per (dst,rel) in-degree
__device__ float    g_rinv[M];                    // 1/max(cnt,1)
__device__ int      g_rowstart[M];                // CSR starts
__device__ int      g_cursor[M];                  // fill cursors
__device__ int      g_bsum[NSB];
__device__ int      g_boff[NSB];
__device__ unsigned short g_erec[E];              // packed (type | t<<8)
__device__ float    g_segsum[G * D];
__device__ float    g_segcnt[G];
__device__ int      g_is64;

// ---------------------------------------------------------------------------
__device__ __forceinline__ long long ldidx(const void* p, long long i, int is64) {
    if (is64) return ((const long long*)p)[i];
    return (long long)((const int*)p)[i];
}

// ---------------------------------------------------------------------------
// Zero accumulators + int64 detection (fused).
// ---------------------------------------------------------------------------
__global__ void k_zero(const unsigned* ei_words) {
    int i = blockIdx.x * blockDim.x + threadIdx.x;
    if (i < M)     g_cnt[i] = 0;
    if (i < G * D) g_segsum[i] = 0.0f;
    if (i < G)     g_segcnt[i] = 0.0f;
    if (i == 0) {
        int is64 = 1;
        for (int k = 0; k < 64; k++) {
            if (ei_words[2 * k + 1] != 0u) { is64 = 0; break; }
        }
        g_is64 = is64;
    }
}

// ---------------------------------------------------------------------------
// Histogram: in-degree per (dst, rel)
// ---------------------------------------------------------------------------
__global__ void k_count(const void* ei, const void* et) {
    int e = blockIdx.x * blockDim.x + threadIdx.x;
    if (e >= E) return;
    int is64 = g_is64;
    int dst = (int)ldidx(ei, (long long)E + e, is64);
    int t   = (int)ldidx(et, e, is64);
    atomicAdd(&g_cnt[dst * NREL + t], 1);
}

// ---------------------------------------------------------------------------
// Exclusive scan (3 kernels) + rinv precompute.
// ---------------------------------------------------------------------------
__global__ void __launch_bounds__(SBLK) k_scan1() {
    __shared__ int sm[SBLK];
    int t = threadIdx.x;
    int i = blockIdx.x * SBLK + t;
    int v = (i < M) ? g_cnt[i] : 0;
    sm[t] = v;
    __syncthreads();
    #pragma unroll
    for (int off = 1; off < SBLK; off <<= 1) {
        int x = (t >= off) ? sm[t - off] : 0;
        __syncthreads();
        sm[t] += x;
        __syncthreads();
    }
    if (i < M) g_rowstart[i] = sm[t] - v;
    if (t == SBLK - 1) g_bsum[blockIdx.x] = sm[t];
}

__global__ void __launch_bounds__(SBLK) k_scan2() {
    __shared__ int sm[SBLK];
    int t = threadIdx.x;
    int v = (t < NSB) ? g_bsum[t] : 0;
    sm[t] = v;
    __syncthreads();
    #pragma unroll
    for (int off = 1; off < SBLK; off <<= 1) {
        int x = (t >= off) ? sm[t - off] : 0;
        __syncthreads();
        sm[t] += x;
        __syncthreads();
    }
    if (t < NSB) g_boff[t] = sm[t] - v;
}

__global__ void __launch_bounds__(SBLK) k_scan3() {
    int i = blockIdx.x * SBLK + threadIdx.x;
    if (i >= M) return;
    int val = g_rowstart[i] + g_boff[i >> 10];
    g_rowstart[i] = val;
    g_cursor[i]   = val;
    int c = g_cnt[i];
    g_rinv[i] = 1.0f / (float)(c > 0 ? c : 1);
}

// ---------------------------------------------------------------------------
// Fill: bucket edges by (dst, rel); record stores SRC TYPE (not id) + rel.
// ---------------------------------------------------------------------------
__global__ void k_fill(const void* ei, const void* et, const void* x) {
    int e = blockIdx.x * blockDim.x + threadIdx.x;
    if (e >= E) return;
    int is64 = g_is64;
    int src = (int)ldidx(ei, e, is64);
    int dst = (int)ldidx(ei, (long long)E + e, is64);
    int t   = (int)ldidx(et, e, is64);
    int typ = (int)ldidx(x, src, is64);            // 0..249
    int pos = atomicAdd(&g_cursor[dst * NREL + t], 1);
    g_erec[pos] = (unsigned short)(typ | (t << 8));
}

// ---------------------------------------------------------------------------
// Type-table transform GEMM (bf16 m16n8k16) — only 250 rows!
//   grid = (2, 9): tile in {0,1} covers 128 type rows; ct<8 -> xrt[ct],
//   ct=8 -> root_table (+bias). Same verified fragment mapping as before.
// ---------------------------------------------------------------------------
__device__ __forceinline__ unsigned packbf2(float lo, float hi) {
    __nv_bfloat162 p = __float22bfloat162_rn(make_float2(lo, hi));
    return *(unsigned*)&p;
}

static constexpr int LDX = 132;  // padded X row stride (floats)
static constexpr int WST = 68;   // padded Wb row stride (bf16x2 words)

__global__ void __launch_bounds__(256) k_table(
    const float* emb, const float* wrel, const float* wroot, const float* bias)
{
    extern __shared__ float smem[];
    unsigned* Wb = (unsigned*)smem;          // [128][68] bf16x2: Wb[n][kp]
    float* Xs = smem + 8704;                 // [128][132] fp32

    const int tid  = threadIdx.x;
    const int tile = blockIdx.x;             // 0 or 1
    const int ct   = blockIdx.y;

    // Pack W: Wb[n][kp] = bf16x2(W[2kp][n], W[2kp+1][n])
    const float* W = (ct < 8) ? (wrel + (size_t)ct * D * D) : wroot;
    for (int i = tid; i < 128 * 64; i += 256) {
        int n  = i & 127;
        int kp = i >> 7;
        Wb[n * WST + kp] = packbf2(W[(2 * kp) * D + n], W[(2 * kp + 1) * D + n]);
    }
    // Load X: rows are type ids directly (pad rows -> 0)
    for (int i = tid; i < 128 * 128; i += 256) {
        int r = i >> 7, c = i & 127;
        int typ = tile * 128 + r;
        Xs[r * LDX + c] = (typ < NTYPE) ? emb[(size_t)typ * D + c] : 0.0f;
    }
    __syncthreads();

    const int warp = tid >> 5, lane = tid & 31;
    const int wrow = (warp >> 1) * 32;
    const int wcol = (warp & 1) * 64;
    const int lg = lane >> 2;
    const int lt = lane & 3;

    float c_[2][8][4];
    #pragma unroll
    for (int mi = 0; mi < 2; mi++)
        #pragma unroll
        for (int ni = 0; ni < 8; ni++)
            #pragma unroll
            for (int q = 0; q < 4; q++) c_[mi][ni][q] = 0.0f;

    #pragma unroll
    for (int k0 = 0; k0 < 128; k0 += 16) {
        unsigned a[2][4], b[8][2];
        const int kp0 = k0 >> 1;
        #pragma unroll
        for (int mi = 0; mi < 2; mi++) {
            int r0 = wrow + mi * 16 + lg;
            const float* x0 = Xs + r0 * LDX + k0 + 2 * lt;
            const float* x1 = Xs + (r0 + 8) * LDX + k0 + 2 * lt;
            float2 f00 = *(const float2*)(x0);
            float2 f10 = *(const float2*)(x1);
            float2 f01 = *(const float2*)(x0 + 8);
            float2 f11 = *(const float2*)(x1 + 8);
            a[mi][0] = packbf2(f00.x, f00.y);
            a[mi][1] = packbf2(f10.x, f10.y);
            a[mi][2] = packbf2(f01.x, f01.y);
            a[mi][3] = packbf2(f11.x, f11.y);
        }
        #pragma unroll
        for (int ni = 0; ni < 8; ni++) {
            int col = wcol + ni * 8 + lg;
            b[ni][0] = Wb[col * WST + kp0 + lt];
            b[ni][1] = Wb[col * WST + kp0 + lt + 4];
        }
        #pragma unroll
        for (int mi = 0; mi < 2; mi++) {
            #pragma unroll
            for (int ni = 0; ni < 8; ni++) {
                asm volatile(
                    "mma.sync.aligned.m16n8k16.row.col.f32.bf16.bf16.f32 "
                    "{%0,%1,%2,%3}, {%4,%5,%6,%7}, {%8,%9}, {%0,%1,%2,%3};"
                    : "+f"(c_[mi][ni][0]), "+f"(c_[mi][ni][1]),
                      "+f"(c_[mi][ni][2]), "+f"(c_[mi][ni][3])
                    : "r"(a[mi][0]), "r"(a[mi][1]), "r"(a[mi][2]), "r"(a[mi][3]),
                      "r"(b[ni][0]), "r"(b[ni][1]));
            }
        }
    }

    const int rb = tile * 128;
    #pragma unroll
    for (int mi = 0; mi < 2; mi++) {
        #pragma unroll
        for (int ni = 0; ni < 8; ni++) {
            int row = rb + wrow + mi * 16 + lg;      // type id, <256
            int col = wcol + ni * 8 + 2 * lt;
            float c0 = c_[mi][ni][0], c1 = c_[mi][ni][1];
            float c2 = c_[mi][ni][2], c3 = c_[mi][ni][3];
            if (ct < 8) {
                __nv_bfloat16* base = g_xrt + ((size_t)ct * TPAD + row) * D;
                *(__nv_bfloat162*)(base + col) =
                    __float22bfloat162_rn(make_float2(c0, c1));
                *(__nv_bfloat162*)(base + 8 * D + col) =
                    __float22bfloat162_rn(make_float2(c2, c3));
            } else {
                float* base = g_root + (size_t)row * D;
                float b0 = bias[col], b1 = bias[col + 1];
                *(float2*)(base + col)         = make_float2(c0 + b0, c1 + b1);
                *(float2*)(base + 8 * D + col) = make_float2(c2 + b0, c3 + b1);
            }
        }
    }
}

// ---------------------------------------------------------------------------
// Pull-aggregation + fused pool. One warp per dst node. Gathers now hit the
// 512 KB L2-resident (partially L1) xrt table; seed = root_table[x[dst]].
// ---------------------------------------------------------------------------
__global__ void __launch_bounds__(256) k_aggpool(const void* x, const void* batch,
                                                 const void* ntype) {
    const int lane = threadIdx.x & 31;
    const int dst  = blockIdx.x * 8 + (threadIdx.x >> 5);
    if (dst >= N) return;
    const int is64 = g_is64;
    const int key0 = dst * NREL;

    const int s   = g_rowstart[key0];
    const int epd = (key0 + NREL < M) ? g_rowstart[key0 + NREL] : E;

    float a0 = 0.0f, a1 = 0.0f, a2 = 0.0f, a3 = 0.0f;

    int i = s;
    for (; i + 4 <= epd; i += 4) {
        unsigned r0i = g_erec[i + 0];
        unsigned r1i = g_erec[i + 1];
        unsigned r2i = g_erec[i + 2];
        unsigned r3i = g_erec[i + 3];
        int t0 = r0i >> 8, t1 = r1i >> 8, t2 = r2i >> 8, t3 = r3i >> 8;
        float v0 = g_rinv[key0 + t0];
        float v1 = g_rinv[key0 + t1];
        float v2 = g_rinv[key0 + t2];
        float v3 = g_rinv[key0 + t3];
        // row index in table = t*TPAD + type = (rec>>8)*256 + (rec&255) = full rec value
        uint2 r0 = ((const uint2*)(g_xrt + (size_t)((t0 << 8) | (r0i & 255)) * D))[lane];
        uint2 r1 = ((const uint2*)(g_xrt + (size_t)((t1 << 8) | (r1i & 255)) * D))[lane];
        uint2 r2 = ((const uint2*)(g_xrt + (size_t)((t2 << 8) | (r2i & 255)) * D))[lane];
        uint2 r3 = ((const uint2*)(g_xrt + (size_t)((t3 << 8) | (r3i & 255)) * D))[lane];
        float2 f;
        f = __bfloat1622float2(*(__nv_bfloat162*)&r0.x); a0 = fmaf(f.x, v0, a0); a1 = fmaf(f.y, v0, a1);
        f = __bfloat1622float2(*(__nv_bfloat162*)&r0.y); a2 = fmaf(f.x, v0, a2); a3 = fmaf(f.y, v0, a3);
        f = __bfloat1622float2(*(__nv_bfloat162*)&r1.x); a0 = fmaf(f.x, v1, a0); a1 = fmaf(f.y, v1, a1);
        f = __bfloat1622float2(*(__nv_bfloat162*)&r1.y); a2 = fmaf(f.x, v1, a2); a3 = fmaf(f.y, v1, a3);
        f = __bfloat1622float2(*(__nv_bfloat162*)&r2.x); a0 = fmaf(f.x, v2, a0); a1 = fmaf(f.y, v2, a1);
        f = __bfloat1622float2(*(__nv_bfloat162*)&r2.y); a2 = fmaf(f.x, v2, a2); a3 = fmaf(f.y, v2, a3);
        f = __bfloat1622float2(*(__nv_bfloat162*)&r3.x); a0 = fmaf(f.x, v3, a0); a1 = fmaf(f.y, v3, a1);
        f = __bfloat1622float2(*(__nv_bfloat162*)&r3.y); a2 = fmaf(f.x, v3, a2); a3 = fmaf(f.y, v3, a3);
    }
    for (; i < epd; i++) {
        unsigned rec = g_erec[i];
        int t = rec >> 8;
        float inv = g_rinv[key0 + t];
        uint2 rv = ((const uint2*)(g_xrt + (size_t)rec * D))[lane];
        float2 f0 = __bfloat1622float2(*(__nv_bfloat162*)&rv.x);
        float2 f1 = __bfloat1622float2(*(__nv_bfloat162*)&rv.y);
        a0 = fmaf(f0.x, inv, a0);
        a1 = fmaf(f0.y, inv, a1);
        a2 = fmaf(f1.x, inv, a2);
        a3 = fmaf(f1.y, inv, a3);
    }

    int typ = (int)ldidx(x, dst, is64);
    float4 seed = *(const float4*)(g_root + (size_t)typ * D + lane * 4);
    float h0 = fmaxf(a0 + seed.x, 0.0f);
    float h1 = fmaxf(a1 + seed.y, 0.0f);
    float h2 = fmaxf(a2 + seed.z, 0.0f);
    float h3 = fmaxf(a3 + seed.w, 0.0f);

    long long nt = ldidx(ntype, dst, is64);
    if (nt == 0) {
        long long g = ldidx(batch, dst, is64);
        float* dp = g_segsum + (int)g * D + lane * 4;
        asm volatile("red.global.add.v4.f32 [%0], {%1,%2,%3,%4};"
                     :: "l"(dp), "f"(h0), "f"(h1), "f"(h2), "f"(h3)
                     : "memory");
        if (lane == 0) atomicAdd(&g_segcnt[(int)g], 1.0f);
    }
}

// ---------------------------------------------------------------------------
// Final: out[g] = (segsum[g]/max(cnt,1)) @ lin_w^T + lin_b
// ---------------------------------------------------------------------------
__global__ void __launch_bounds__(128) k_final(const float* linw, const float* linb,
                                               float* out) {
    __shared__ float gv[D];
    const int g = blockIdx.x, tid = threadIdx.x;
    float cnt = g_segcnt[g];
    float inv = 1.0f / fmaxf(cnt, 1.0f);
    gv[tid] = g_segsum[g * D + tid] * inv;
    __syncthreads();
    if (tid < NC) {
        float s = linb[tid];
        const float* w = linw + tid * D;
        #pragma unroll 8
        for (int h = 0; h < D; h++) s += gv[h] * w[h];
        out[g * NC + tid] = s;
    }
}

// ---------------------------------------------------------------------------
extern "C" void kernel_launch(void* const* d_in, const int* in_sizes, int n_in,
                              void* d_out, int out_size) {
    // Input order: x, edge_index, edge_type, batch, node_type,
    //              [num_graphs scalar], node_emb_w, w_root, w_rel,
    //              conv_bias, lin_w, lin_b
    int off = (n_in >= 12) ? 1 : 0;
    const void* x     = d_in[0];
    const void* ei    = d_in[1];
    const void* et    = d_in[2];
    const void* batch = d_in[3];
    const void* ntype = d_in[4];
    const float* emb   = (const float*)d_in[5 + off];
    const float* wroot = (const float*)d_in[6 + off];
    const float* wrel  = (const float*)d_in[7 + off];
    const float* bias  = (const float*)d_in[8 + off];
    const float* linw  = (const float*)d_in[9 + off];
    const float* linb  = (const float*)d_in[10 + off];
    float* out = (float*)d_out;

    // Wb (128*68 words) + Xs (128*132 floats) = 102400 bytes
    const int smem_bytes = (8704 + 128 * LDX) * (int)sizeof(float);
    cudaFuncSetAttribute(k_table, cudaFuncAttributeMaxDynamicSharedMemorySize,
                         smem_bytes);

    k_zero<<<(M + 255) / 256, 256>>>((const unsigned*)ei);
    k_table<<<dim3(2, 9), 256, smem_bytes>>>(emb, wrel, wroot, bias);
    k_count<<<(E + 255) / 256, 256>>>(ei, et);
    k_scan1<<<NSB, SBLK>>>();
    k_scan2<<<1, SBLK>>>();
    k_scan3<<<NSB, SBLK>>>();
    k_fill<<<(E + 255) / 256, 256>>>(ei, et, x);
    k_aggpool<<<(N + 7) / 8, 256>>>(x, batch, ntype);
    k_final<<<G, 128>>>(linw, linb, out);
}